// round 3
// baseline (speedup 1.0000x reference)
#include <cuda_runtime.h>
#include <math.h>

// ============================================================================
// CormorantCGProduct: full CG tensor product of two SO(3) vector arrays.
// LMAX=3, N=1024, TAU=16.
// Output layout (concatenation of the 4 degree arrays, C-order each):
//   out_l shape (2, N, 2l+1, NPART[l]*256), channel = part*256 + c*16 + d
// ============================================================================

#define LMAX   3
#define NN     1024
#define TAU    16
#define NTOT   3436   // total dense CG table size over all (l1,l2,l) triples

__device__ float g_cg[NTOT];

// ----------------------------------------------------------------------------
// Clebsch-Gordan coefficient (Condon-Shortley), computed on device in double.
// ----------------------------------------------------------------------------
__device__ __forceinline__ double dfact(int n) {
    double r = 1.0;
    for (int i = 2; i <= n; ++i) r *= (double)i;
    return r;
}

__device__ double cg_coef(int j1, int m1, int j2, int m2, int j, int m) {
    if (m1 + m2 != m) return 0.0;
    int dj = j1 - j2; if (dj < 0) dj = -dj;
    if (j < dj || j > j1 + j2) return 0.0;
    double pref = sqrt((2.0 * j + 1.0)
        * dfact(j + j1 - j2) * dfact(j - j1 + j2) * dfact(j1 + j2 - j) / dfact(j1 + j2 + j + 1)
        * dfact(j + m) * dfact(j - m) * dfact(j1 - m1) * dfact(j1 + m1)
        * dfact(j2 - m2) * dfact(j2 + m2));
    int kmin = 0;
    if (j2 - j - m1 > kmin) kmin = j2 - j - m1;
    if (j1 - j + m2 > kmin) kmin = j1 - j + m2;
    int kmax = j1 + j2 - j;
    if (j1 - m1 < kmax) kmax = j1 - m1;
    if (j2 + m2 < kmax) kmax = j2 + m2;
    double s = 0.0;
    for (int k = kmin; k <= kmax; ++k) {
        double den = dfact(k) * dfact(j1 + j2 - j - k) * dfact(j1 - m1 - k)
                   * dfact(j2 + m2 - k) * dfact(j - j2 + m1 + k) * dfact(j - j1 - m2 + k);
        s += ((k & 1) ? -1.0 : 1.0) / den;
    }
    return pref * s;
}

// Fill the dense CG table (runs every launch; deterministic; ~3.4K entries).
__global__ void init_cg_kernel() {
    int idx = blockIdx.x * blockDim.x + threadIdx.x;
    if (idx >= NTOT) return;
    int base = 0;
    for (int l1 = 0; l1 <= LMAX; ++l1)
        for (int l2 = 0; l2 <= LMAX; ++l2) {
            int lo = (l1 > l2) ? (l1 - l2) : (l2 - l1);
            int hi = (l1 + l2 < LMAX) ? (l1 + l2) : LMAX;
            for (int l = lo; l <= hi; ++l) {
                int sz = (2 * l1 + 1) * (2 * l2 + 1) * (2 * l + 1);
                if (idx < base + sz) {
                    int loc = idx - base;
                    int z = loc % (2 * l + 1);
                    int y = (loc / (2 * l + 1)) % (2 * l2 + 1);
                    int x = loc / ((2 * l + 1) * (2 * l2 + 1));
                    g_cg[idx] = (float)cg_coef(l1, x - l1, l2, y - l2, l, z - l);
                    return;
                }
                base += sz;
            }
        }
}

// ----------------------------------------------------------------------------
// Compile-time layout helpers (pure integer; folded after #pragma unroll).
// ----------------------------------------------------------------------------
__host__ __device__ __forceinline__ constexpr int tri_base(int L1, int L2, int L) {
    int b = 0;
    for (int l1 = 0; l1 <= LMAX; ++l1)
        for (int l2 = 0; l2 <= LMAX; ++l2) {
            int lo = (l1 > l2) ? (l1 - l2) : (l2 - l1);
            int hi = (l1 + l2 < LMAX) ? (l1 + l2) : LMAX;
            for (int l = lo; l <= hi; ++l) {
                if (l1 == L1 && l2 == L2 && l == L) return b;
                b += (2 * l1 + 1) * (2 * l2 + 1) * (2 * l + 1);
            }
        }
    return 0;
}

__host__ __device__ __forceinline__ constexpr int part_index(int L1, int L2, int L) {
    int p = 0;
    for (int l1 = 0; l1 <= LMAX; ++l1)
        for (int l2 = 0; l2 <= LMAX; ++l2) {
            int lo = (l1 > l2) ? (l1 - l2) : (l2 - l1);
            int hi = (l1 + l2 < LMAX) ? (l1 + l2) : LMAX;
            if (L >= lo && L <= hi) {
                if (l1 == L1 && l2 == L2) return p;
                ++p;
            }
        }
    return 0;
}

__host__ __device__ __forceinline__ constexpr int npart(int l) {
    return (l == 0) ? 4 : (l == 1) ? 9 : (l == 2) ? 11 : 10;
}

__host__ __device__ __forceinline__ constexpr int lbase(int l) {
    // cumulative float offsets of the 4 degree blocks
    int b = 0;
    for (int k = 0; k < l; ++k) b += 2 * NN * (2 * k + 1) * npart(k) * 256;
    return b;   // l0:0  l1:2097152  l2:16252928  l3:45088768
}

// ----------------------------------------------------------------------------
// Per-(l1,l2) compute: complex outer product + sparse CG contraction + stores.
// ----------------------------------------------------------------------------
template <int L1, int L2>
__device__ __forceinline__ void do_pair(
    const float* __restrict__ sA, const float* __restrict__ sB,
    const float* __restrict__ scg, float* __restrict__ out,
    int n, int tid, int c, int d)
{
    constexpr int D1   = 2 * L1 + 1;
    constexpr int D2   = 2 * L2 + 1;
    constexpr int LMIN = (L1 > L2) ? (L1 - L2) : (L2 - L1);
    constexpr int LHI  = (L1 + L2 < LMAX) ? (L1 + L2) : LMAX;
    constexpr int NL   = LHI - LMIN + 1;

    float ar[D1], ai[D1], br[D2], bi[D2];
#pragma unroll
    for (int x = 0; x < D1; ++x) {
        ar[x] = sA[(L1 * L1 + x) * TAU + c];
        ai[x] = sA[256 + (L1 * L1 + x) * TAU + c];
    }
#pragma unroll
    for (int y = 0; y < D2; ++y) {
        br[y] = sB[(L2 * L2 + y) * TAU + d];
        bi[y] = sB[256 + (L2 * L2 + y) * TAU + d];
    }

    float accR[NL][2 * LHI + 1];
    float accI[NL][2 * LHI + 1];
#pragma unroll
    for (int i = 0; i < NL; ++i) {
#pragma unroll
        for (int z = 0; z < 2 * LHI + 1; ++z) { accR[i][z] = 0.f; accI[i][z] = 0.f; }
    }

#pragma unroll
    for (int x = 0; x < D1; ++x) {
#pragma unroll
        for (int y = 0; y < D2; ++y) {
            const float pr = ar[x] * br[y] - ai[x] * bi[y];
            const float pi = ar[x] * bi[y] + ai[x] * br[y];
            const int m = (x - L1) + (y - L2);
#pragma unroll
            for (int li = 0; li < NL; ++li) {
                const int l = LMIN + li;
                if (m >= -l && m <= l) {
                    const float cg = scg[tri_base(L1, L2, l) + (x * D2 + y) * (2 * l + 1) + (m + l)];
                    accR[li][m + l] += cg * pr;
                    accI[li][m + l] += cg * pi;
                }
            }
        }
    }

#pragma unroll
    for (int li = 0; li < NL; ++li) {
        const int l    = LMIN + li;
        const int taul = npart(l) * 256;
        const int base = lbase(l) + part_index(L1, L2, l) * 256 + tid;
#pragma unroll
        for (int z = 0; z < 2 * l + 1; ++z) {
            out[base + (n        * (2 * l + 1) + z) * taul] = accR[li][z];   // real
            out[base + ((NN + n) * (2 * l + 1) + z) * taul] = accI[li][z];   // imag
        }
    }
}

// ----------------------------------------------------------------------------
// Main kernel: one block per n; thread = (c,d) so ch = tid (coalesced stores).
// ----------------------------------------------------------------------------
__global__ __launch_bounds__(256)
void cg_product_kernel(
    const float* __restrict__ A0, const float* __restrict__ A1,
    const float* __restrict__ A2, const float* __restrict__ A3,
    const float* __restrict__ B0, const float* __restrict__ B1,
    const float* __restrict__ B2, const float* __restrict__ B3,
    float* __restrict__ out)
{
    __shared__ float sA[2 * 16 * TAU];   // [ri][xflat][tau]
    __shared__ float sB[2 * 16 * TAU];
    __shared__ float scg[NTOT];

    const int n   = blockIdx.x;
    const int tid = threadIdx.x;
    const int c   = tid >> 4;
    const int d   = tid & 15;

    const float* Ap[4] = {A0, A1, A2, A3};
    const float* Bp[4] = {B0, B1, B2, B3};

    // Stage A/B values for this n: 512 floats each, cooperative, coalesced.
    for (int j = tid; j < 512; j += 256) {
        int ri = j >> 8, xf = (j >> 4) & 15, ch = j & 15;
        int l = (xf == 0) ? 0 : ((xf < 4) ? 1 : ((xf < 9) ? 2 : 3));
        int x = xf - l * l;
        int dim = 2 * l + 1;
        int src = ((ri * NN + n) * dim + x) * TAU + ch;
        sA[j] = Ap[l][src];
        sB[j] = Bp[l][src];
    }
    // Stage CG table into shared memory.
    for (int j = tid; j < NTOT; j += 256) scg[j] = g_cg[j];
    __syncthreads();

    do_pair<0, 0>(sA, sB, scg, out, n, tid, c, d);
    do_pair<0, 1>(sA, sB, scg, out, n, tid, c, d);
    do_pair<0, 2>(sA, sB, scg, out, n, tid, c, d);
    do_pair<0, 3>(sA, sB, scg, out, n, tid, c, d);
    do_pair<1, 0>(sA, sB, scg, out, n, tid, c, d);
    do_pair<1, 1>(sA, sB, scg, out, n, tid, c, d);
    do_pair<1, 2>(sA, sB, scg, out, n, tid, c, d);
    do_pair<1, 3>(sA, sB, scg, out, n, tid, c, d);
    do_pair<2, 0>(sA, sB, scg, out, n, tid, c, d);
    do_pair<2, 1>(sA, sB, scg, out, n, tid, c, d);
    do_pair<2, 2>(sA, sB, scg, out, n, tid, c, d);
    do_pair<2, 3>(sA, sB, scg, out, n, tid, c, d);
    do_pair<3, 0>(sA, sB, scg, out, n, tid, c, d);
    do_pair<3, 1>(sA, sB, scg, out, n, tid, c, d);
    do_pair<3, 2>(sA, sB, scg, out, n, tid, c, d);
    do_pair<3, 3>(sA, sB, scg, out, n, tid, c, d);
}

// ----------------------------------------------------------------------------
// Launch: identify inputs by element count (A before B per degree — robust to
// either A0,B0,A1,B1,... or A0..A3,B0..B3 metadata ordering).
// ----------------------------------------------------------------------------
extern "C" void kernel_launch(void* const* d_in, const int* in_sizes, int n_in,
                              void* d_out, int out_size)
{
    const float* A[4] = {nullptr, nullptr, nullptr, nullptr};
    const float* B[4] = {nullptr, nullptr, nullptr, nullptr};
    for (int i = 0; i < n_in; ++i) {
        int sz = in_sizes[i];
        for (int l = 0; l <= LMAX; ++l) {
            if (sz == 2 * NN * (2 * l + 1) * TAU) {
                if (!A[l]) A[l] = (const float*)d_in[i];
                else if (!B[l]) B[l] = (const float*)d_in[i];
            }
        }
    }

    init_cg_kernel<<<(NTOT + 255) / 256, 256>>>();
    cg_product_kernel<<<NN, 256>>>(
        A[0], A[1], A[2], A[3],
        B[0], B[1], B[2], B[3],
        (float*)d_out);
}

// round 4
// speedup vs baseline: 1.1141x; 1.1141x over previous
#include <cuda_runtime.h>

// ============================================================================
// CormorantCGProduct: full CG tensor product of two SO(3) vector arrays.
// LMAX=3, N=1024, TAU=16.
// Output: concatenation of 4 degree blocks, each (2, N, 2l+1, NPART[l]*256),
// channel = part*256 + c*16 + d  (part ordered by (l1,l2) lexicographic).
//
// Strategy: one block per (n, pair); pair = (l1,l2) selected by blockIdx.y.
// CG coefficients computed entirely at COMPILE TIME (constexpr) and baked
// into __constant__ memory — no init kernel, no smem, no barriers.
// Per-output-l accumulation keeps register pressure ~60 (no spills).
// ============================================================================

#define LMAX   3
#define NN     1024
#define TAU    16
#define NTOT   3436   // total dense CG table size over all (l1,l2,l) triples

// ----------------------------------------------------------------------------
// Compile-time Clebsch-Gordan coefficients (Condon-Shortley), double precision.
// ----------------------------------------------------------------------------
constexpr double cfact(int n) {
    double r = 1.0;
    for (int i = 2; i <= n; ++i) r *= (double)i;
    return r;
}

constexpr double csqrt(double x) {
    double g = (x > 1.0) ? x : 1.0;
    for (int i = 0; i < 80; ++i) g = 0.5 * (g + x / g);
    return g;
}

constexpr double cg_coef(int j1, int m1, int j2, int m2, int j, int m) {
    if (m1 + m2 != m) return 0.0;
    int dj = (j1 > j2) ? (j1 - j2) : (j2 - j1);
    if (j < dj || j > j1 + j2) return 0.0;
    double pref = csqrt((2.0 * j + 1.0)
        * cfact(j + j1 - j2) * cfact(j - j1 + j2) * cfact(j1 + j2 - j) / cfact(j1 + j2 + j + 1)
        * cfact(j + m) * cfact(j - m) * cfact(j1 - m1) * cfact(j1 + m1)
        * cfact(j2 - m2) * cfact(j2 + m2));
    int kmin = 0;
    if (j2 - j - m1 > kmin) kmin = j2 - j - m1;
    if (j1 - j + m2 > kmin) kmin = j1 - j + m2;
    int kmax = j1 + j2 - j;
    if (j1 - m1 < kmax) kmax = j1 - m1;
    if (j2 + m2 < kmax) kmax = j2 + m2;
    double s = 0.0;
    for (int k = kmin; k <= kmax; ++k) {
        double den = cfact(k) * cfact(j1 + j2 - j - k) * cfact(j1 - m1 - k)
                   * cfact(j2 + m2 - k) * cfact(j - j2 + m1 + k) * cfact(j - j1 - m2 + k);
        s += ((k & 1) ? -1.0 : 1.0) / den;
    }
    return pref * s;
}

struct CGTab { float v[NTOT]; };

constexpr CGTab make_cg() {
    CGTab t{};
    int base = 0;
    for (int l1 = 0; l1 <= LMAX; ++l1)
        for (int l2 = 0; l2 <= LMAX; ++l2) {
            int lo = (l1 > l2) ? (l1 - l2) : (l2 - l1);
            int hi = (l1 + l2 < LMAX) ? (l1 + l2) : LMAX;
            for (int l = lo; l <= hi; ++l) {
                for (int x = 0; x < 2 * l1 + 1; ++x)
                    for (int y = 0; y < 2 * l2 + 1; ++y)
                        for (int z = 0; z < 2 * l + 1; ++z)
                            t.v[base + (x * (2 * l2 + 1) + y) * (2 * l + 1) + z] =
                                (float)cg_coef(l1, x - l1, l2, y - l2, l, z - l);
                base += (2 * l1 + 1) * (2 * l2 + 1) * (2 * l + 1);
            }
        }
    return t;
}

// Static (compile-time) initialization — no runtime work, no allocation.
__constant__ CGTab c_cg = make_cg();

// ----------------------------------------------------------------------------
// Compile-time layout helpers (folded to immediates after unrolling).
// ----------------------------------------------------------------------------
__host__ __device__ __forceinline__ constexpr int tri_base(int L1, int L2, int L) {
    int b = 0;
    for (int l1 = 0; l1 <= LMAX; ++l1)
        for (int l2 = 0; l2 <= LMAX; ++l2) {
            int lo = (l1 > l2) ? (l1 - l2) : (l2 - l1);
            int hi = (l1 + l2 < LMAX) ? (l1 + l2) : LMAX;
            for (int l = lo; l <= hi; ++l) {
                if (l1 == L1 && l2 == L2 && l == L) return b;
                b += (2 * l1 + 1) * (2 * l2 + 1) * (2 * l + 1);
            }
        }
    return 0;
}

__host__ __device__ __forceinline__ constexpr int part_index(int L1, int L2, int L) {
    int p = 0;
    for (int l1 = 0; l1 <= LMAX; ++l1)
        for (int l2 = 0; l2 <= LMAX; ++l2) {
            int lo = (l1 > l2) ? (l1 - l2) : (l2 - l1);
            int hi = (l1 + l2 < LMAX) ? (l1 + l2) : LMAX;
            if (L >= lo && L <= hi) {
                if (l1 == L1 && l2 == L2) return p;
                ++p;
            }
        }
    return 0;
}

__host__ __device__ __forceinline__ constexpr int npart(int l) {
    return (l == 0) ? 4 : (l == 1) ? 9 : (l == 2) ? 11 : 10;
}

__host__ __device__ __forceinline__ constexpr int lbase(int l) {
    int b = 0;
    for (int k = 0; k < l; ++k) b += 2 * NN * (2 * k + 1) * npart(k) * 256;
    return b;   // l0:0  l1:2097152  l2:16252928  l3:45088768
}

// ----------------------------------------------------------------------------
// One (l1,l2) pair for one n. Per-output-l accumulation: only ar/ai/br/bi plus
// a single l's accumulators are live at once -> low register pressure.
// ----------------------------------------------------------------------------
template <int L1, int L2>
__device__ __forceinline__ void do_pair(
    const float* __restrict__ A, const float* __restrict__ B,
    float* __restrict__ out, int n, int tid)
{
    constexpr int D1   = 2 * L1 + 1;
    constexpr int D2   = 2 * L2 + 1;
    constexpr int LMIN = (L1 > L2) ? (L1 - L2) : (L2 - L1);
    constexpr int LHI  = (L1 + L2 < LMAX) ? (L1 + L2) : LMAX;

    const int c = tid >> 4;
    const int d = tid & 15;

    float ar[D1], ai[D1], br[D2], bi[D2];
#pragma unroll
    for (int x = 0; x < D1; ++x) {
        ar[x] = A[(n * D1 + x) * TAU + c];
        ai[x] = A[((NN + n) * D1 + x) * TAU + c];
    }
#pragma unroll
    for (int y = 0; y < D2; ++y) {
        br[y] = B[(n * D2 + y) * TAU + d];
        bi[y] = B[((NN + n) * D2 + y) * TAU + d];
    }

#pragma unroll
    for (int l = LMIN; l <= LHI; ++l) {
        float accR[2 * LHI + 1];
        float accI[2 * LHI + 1];
#pragma unroll
        for (int z = 0; z < 2 * l + 1; ++z) { accR[z] = 0.f; accI[z] = 0.f; }

#pragma unroll
        for (int x = 0; x < D1; ++x) {
#pragma unroll
            for (int y = 0; y < D2; ++y) {
                const int m = (x - L1) + (y - L2);
                if (m >= -l && m <= l) {          // compile-time after unroll
                    const float pr = ar[x] * br[y] - ai[x] * bi[y];
                    const float pi = ar[x] * bi[y] + ai[x] * br[y];
                    const float cg = c_cg.v[tri_base(L1, L2, l)
                                            + (x * D2 + y) * (2 * l + 1) + (m + l)];
                    accR[m + l] += cg * pr;
                    accI[m + l] += cg * pi;
                }
            }
        }

        const int taul = npart(l) * 256;
        const int base = lbase(l) + part_index(L1, L2, l) * 256 + tid;
#pragma unroll
        for (int z = 0; z < 2 * l + 1; ++z) {
            out[base + (n        * (2 * l + 1) + z) * taul] = accR[z];   // real
            out[base + ((NN + n) * (2 * l + 1) + z) * taul] = accI[z];   // imag
        }
    }
}

// ----------------------------------------------------------------------------
// Main kernel: grid = (N, 16 pairs), block = 256 threads (thread = channel).
// ----------------------------------------------------------------------------
__global__ __launch_bounds__(256)
void cg_pair_kernel(
    const float* __restrict__ A0, const float* __restrict__ A1,
    const float* __restrict__ A2, const float* __restrict__ A3,
    const float* __restrict__ B0, const float* __restrict__ B1,
    const float* __restrict__ B2, const float* __restrict__ B3,
    float* __restrict__ out)
{
    const int n   = blockIdx.x;
    const int tid = threadIdx.x;

    switch (blockIdx.y) {
        case  0: do_pair<0, 0>(A0, B0, out, n, tid); break;
        case  1: do_pair<0, 1>(A0, B1, out, n, tid); break;
        case  2: do_pair<0, 2>(A0, B2, out, n, tid); break;
        case  3: do_pair<0, 3>(A0, B3, out, n, tid); break;
        case  4: do_pair<1, 0>(A1, B0, out, n, tid); break;
        case  5: do_pair<1, 1>(A1, B1, out, n, tid); break;
        case  6: do_pair<1, 2>(A1, B2, out, n, tid); break;
        case  7: do_pair<1, 3>(A1, B3, out, n, tid); break;
        case  8: do_pair<2, 0>(A2, B0, out, n, tid); break;
        case  9: do_pair<2, 1>(A2, B1, out, n, tid); break;
        case 10: do_pair<2, 2>(A2, B2, out, n, tid); break;
        case 11: do_pair<2, 3>(A2, B3, out, n, tid); break;
        case 12: do_pair<3, 0>(A3, B0, out, n, tid); break;
        case 13: do_pair<3, 1>(A3, B1, out, n, tid); break;
        case 14: do_pair<3, 2>(A3, B2, out, n, tid); break;
        default: do_pair<3, 3>(A3, B3, out, n, tid); break;
    }
}

// ----------------------------------------------------------------------------
// Launch: identify inputs by element count (A before B per degree — robust to
// either A0,B0,A1,B1,... or A0..A3,B0..B3 metadata ordering).
// ----------------------------------------------------------------------------
extern "C" void kernel_launch(void* const* d_in, const int* in_sizes, int n_in,
                              void* d_out, int out_size)
{
    const float* A[4] = {nullptr, nullptr, nullptr, nullptr};
    const float* B[4] = {nullptr, nullptr, nullptr, nullptr};
    for (int i = 0; i < n_in; ++i) {
        int sz = in_sizes[i];
        for (int l = 0; l <= LMAX; ++l) {
            if (sz == 2 * NN * (2 * l + 1) * TAU) {
                if (!A[l]) A[l] = (const float*)d_in[i];
                else if (!B[l]) B[l] = (const float*)d_in[i];
            }
        }
    }

    dim3 grid(NN, 16);
    cg_pair_kernel<<<grid, 256>>>(
        A[0], A[1], A[2], A[3],
        B[0], B[1], B[2], B[3],
        (float*)d_out);
}

// round 9
// speedup vs baseline: 17.2018x; 15.4402x over previous
#include <cuda_runtime.h>
#include <type_traits>

// ============================================================================
// CormorantCGProduct: full CG tensor product of two SO(3) vector arrays.
// LMAX=3, N=1024, TAU=16.
// Output: concatenation of 4 degree blocks, each (2, N, 2l+1, NPART[l]*256),
// channel = part*256 + c*16 + d  (part ordered by (l1,l2) lexicographic).
//
// Strategy: every CG coefficient is a COMPILE-TIME float literal baked
// directly into FFMA immediates (no LDC — Blackwell has no cbank ALU operands
// and LDC has an 8-cycle structural floor). Products computed once per (x,y),
// compile-time-zero coefficients skipped, streaming stores.
// All constexpr helpers are __host__ __device__ so no --expt-relaxed-constexpr
// is required.
// ============================================================================

#define LMAX   3
#define NN     1024
#define TAU    16

// ----------------------------------------------------------------------------
// Compile-time Clebsch-Gordan coefficients (Condon-Shortley), double precision.
// ----------------------------------------------------------------------------
__host__ __device__ constexpr double cfact(int n) {
    double r = 1.0;
    for (int i = 2; i <= n; ++i) r *= (double)i;
    return r;
}

__host__ __device__ constexpr double csqrt(double x) {
    double g = (x > 1.0) ? x : 1.0;
    for (int i = 0; i < 60; ++i) g = 0.5 * (g + x / g);
    return g;
}

__host__ __device__ constexpr double cg_coef(int j1, int m1, int j2, int m2, int j, int m) {
    if (m1 + m2 != m) return 0.0;
    int dj = (j1 > j2) ? (j1 - j2) : (j2 - j1);
    if (j < dj || j > j1 + j2) return 0.0;
    double pref = csqrt((2.0 * j + 1.0)
        * cfact(j + j1 - j2) * cfact(j - j1 + j2) * cfact(j1 + j2 - j) / cfact(j1 + j2 + j + 1)
        * cfact(j + m) * cfact(j - m) * cfact(j1 - m1) * cfact(j1 + m1)
        * cfact(j2 - m2) * cfact(j2 + m2));
    int kmin = 0;
    if (j2 - j - m1 > kmin) kmin = j2 - j - m1;
    if (j1 - j + m2 > kmin) kmin = j1 - j + m2;
    int kmax = j1 + j2 - j;
    if (j1 - m1 < kmax) kmax = j1 - m1;
    if (j2 + m2 < kmax) kmax = j2 + m2;
    double s = 0.0;
    for (int k = kmin; k <= kmax; ++k) {
        double den = cfact(k) * cfact(j1 + j2 - j - k) * cfact(j1 - m1 - k)
                   * cfact(j2 + m2 - k) * cfact(j - j2 + m1 + k) * cfact(j - j1 - m2 + k);
        s += ((k & 1) ? -1.0 : 1.0) / den;
    }
    return pref * s;
}

// ----------------------------------------------------------------------------
// Compile-time unrolling with true constant indices.
// ----------------------------------------------------------------------------
template <int N, typename F>
__device__ __forceinline__ void static_for(F&& f) {
    if constexpr (N > 0) {
        static_for<N - 1>(f);
        f(std::integral_constant<int, N - 1>{});
    }
}

// ----------------------------------------------------------------------------
// Compile-time layout helpers.
// ----------------------------------------------------------------------------
__host__ __device__ __forceinline__ constexpr int part_index(int L1, int L2, int L) {
    int p = 0;
    for (int l1 = 0; l1 <= LMAX; ++l1)
        for (int l2 = 0; l2 <= LMAX; ++l2) {
            int lo = (l1 > l2) ? (l1 - l2) : (l2 - l1);
            int hi = (l1 + l2 < LMAX) ? (l1 + l2) : LMAX;
            if (L >= lo && L <= hi) {
                if (l1 == L1 && l2 == L2) return p;
                ++p;
            }
        }
    return 0;
}

__host__ __device__ __forceinline__ constexpr int npart(int l) {
    return (l == 0) ? 4 : (l == 1) ? 9 : (l == 2) ? 11 : 10;
}

__host__ __device__ __forceinline__ constexpr int lbase(int l) {
    int b = 0;
    for (int k = 0; k < l; ++k) b += 2 * NN * (2 * k + 1) * npart(k) * 256;
    return b;   // l0:0  l1:2097152  l2:16252928  l3:45088768
}

// ----------------------------------------------------------------------------
// One (l1,l2) pair for one n. All CG coefficients are FFMA immediates.
// ----------------------------------------------------------------------------
template <int L1, int L2>
__device__ __forceinline__ void do_pair(
    const float* __restrict__ A, const float* __restrict__ B,
    float* __restrict__ out, int n, int tid)
{
    constexpr int D1   = 2 * L1 + 1;
    constexpr int D2   = 2 * L2 + 1;
    constexpr int LMIN = (L1 > L2) ? (L1 - L2) : (L2 - L1);
    constexpr int LHI  = (L1 + L2 < LMAX) ? (L1 + L2) : LMAX;
    constexpr int NL   = LHI - LMIN + 1;

    const int c = tid >> 4;
    const int d = tid & 15;

    float ar[D1], ai[D1], br[D2], bi[D2];
#pragma unroll
    for (int x = 0; x < D1; ++x) {
        ar[x] = __ldg(&A[(n * D1 + x) * TAU + c]);
        ai[x] = __ldg(&A[((NN + n) * D1 + x) * TAU + c]);
    }
#pragma unroll
    for (int y = 0; y < D2; ++y) {
        br[y] = __ldg(&B[(n * D2 + y) * TAU + d]);
        bi[y] = __ldg(&B[((NN + n) * D2 + y) * TAU + d]);
    }

    float accR[NL][2 * LHI + 1];
    float accI[NL][2 * LHI + 1];
#pragma unroll
    for (int i = 0; i < NL; ++i)
#pragma unroll
        for (int z = 0; z < 2 * LHI + 1; ++z) { accR[i][z] = 0.f; accI[i][z] = 0.f; }

    static_for<D1>([&](auto XC) {
        constexpr int x = decltype(XC)::value;
        static_for<D2>([&](auto YC) {
            constexpr int y = decltype(YC)::value;
            constexpr int m = (x - L1) + (y - L2);
            if constexpr (m >= -LHI && m <= LHI) {
                const float pr = ar[x] * br[y] - ai[x] * bi[y];
                const float pi = ar[x] * bi[y] + ai[x] * br[y];
                static_for<NL>([&](auto LC) {
                    constexpr int li = decltype(LC)::value;
                    constexpr int l  = LMIN + li;
                    if constexpr (m >= -l && m <= l) {
                        constexpr float cg =
                            (float)cg_coef(L1, x - L1, L2, y - L2, l, m);
                        if constexpr (cg != 0.0f) {
                            accR[li][m + l] += cg * pr;   // FFMA with immediate
                            accI[li][m + l] += cg * pi;   // FFMA with immediate
                        }
                    }
                });
            }
        });
    });

    static_for<NL>([&](auto LC) {
        constexpr int li   = decltype(LC)::value;
        constexpr int l    = LMIN + li;
        constexpr int taul = npart(l) * 256;
        constexpr int pbase = lbase(l) + part_index(L1, L2, l) * 256;
        float* pR = out + pbase + tid + n * (2 * l + 1) * taul;
        float* pI = pR + NN * (2 * l + 1) * taul;
        static_for<2 * l + 1>([&](auto ZC) {
            constexpr int z = decltype(ZC)::value;
            __stcs(pR + z * taul, accR[li][z]);   // real, streaming
            __stcs(pI + z * taul, accI[li][z]);   // imag, streaming
        });
    });
}

// ----------------------------------------------------------------------------
// Main kernel: grid = (N, 16 pairs), block = 256 threads (thread = channel).
// ----------------------------------------------------------------------------
__global__ __launch_bounds__(256)
void cg_pair_kernel(
    const float* __restrict__ A0, const float* __restrict__ A1,
    const float* __restrict__ A2, const float* __restrict__ A3,
    const float* __restrict__ B0, const float* __restrict__ B1,
    const float* __restrict__ B2, const float* __restrict__ B3,
    float* __restrict__ out)
{
    const int n   = blockIdx.x;
    const int tid = threadIdx.x;

    switch (blockIdx.y) {
        case  0: do_pair<0, 0>(A0, B0, out, n, tid); break;
        case  1: do_pair<0, 1>(A0, B1, out, n, tid); break;
        case  2: do_pair<0, 2>(A0, B2, out, n, tid); break;
        case  3: do_pair<0, 3>(A0, B3, out, n, tid); break;
        case  4: do_pair<1, 0>(A1, B0, out, n, tid); break;
        case  5: do_pair<1, 1>(A1, B1, out, n, tid); break;
        case  6: do_pair<1, 2>(A1, B2, out, n, tid); break;
        case  7: do_pair<1, 3>(A1, B3, out, n, tid); break;
        case  8: do_pair<2, 0>(A2, B0, out, n, tid); break;
        case  9: do_pair<2, 1>(A2, B1, out, n, tid); break;
        case 10: do_pair<2, 2>(A2, B2, out, n, tid); break;
        case 11: do_pair<2, 3>(A2, B3, out, n, tid); break;
        case 12: do_pair<3, 0>(A3, B0, out, n, tid); break;
        case 13: do_pair<3, 1>(A3, B1, out, n, tid); break;
        case 14: do_pair<3, 2>(A3, B2, out, n, tid); break;
        default: do_pair<3, 3>(A3, B3, out, n, tid); break;
    }
}

// ----------------------------------------------------------------------------
// Launch: identify inputs by element count (A before B per degree — robust to
// either A0,B0,A1,B1,... or A0..A3,B0..B3 metadata ordering).
// ----------------------------------------------------------------------------
extern "C" void kernel_launch(void* const* d_in, const int* in_sizes, int n_in,
                              void* d_out, int out_size)
{
    const float* A[4] = {nullptr, nullptr, nullptr, nullptr};
    const float* B[4] = {nullptr, nullptr, nullptr, nullptr};
    for (int i = 0; i < n_in; ++i) {
        int sz = in_sizes[i];
        for (int l = 0; l <= LMAX; ++l) {
            if (sz == 2 * NN * (2 * l + 1) * TAU) {
                if (!A[l]) A[l] = (const float*)d_in[i];
                else if (!B[l]) B[l] = (const float*)d_in[i];
            }
        }
    }

    dim3 grid(NN, 16);
    cg_pair_kernel<<<grid, 256>>>(
        A[0], A[1], A[2], A[3],
        B[0], B[1], B[2], B[3],
        (float*)d_out);
}

// round 10
// speedup vs baseline: 22.5623x; 1.3116x over previous
#include <cuda_runtime.h>
#include <type_traits>

// ============================================================================
// CormorantCGProduct: full CG tensor product of two SO(3) vector arrays.
// LMAX=3, N=1024, TAU=16.
// Output: concatenation of 4 degree blocks, each (2, N, 2l+1, NPART[l]*256),
// channel = part*256 + c*16 + d  (part ordered by (l1,l2) lexicographic).
//
// Round-10: one block per (n, TRIPLE) where triple = (l1,l2,l) — 34 slices.
// Only one output degree's accumulators are live per block -> ~48 regs,
// 5 CTAs/SM (62.5% occ), fine-grained load balance. CG coefficients remain
// compile-time FFMA immediates; streaming stores.
// ============================================================================

#define LMAX   3
#define NN     1024
#define TAU    16

// ----------------------------------------------------------------------------
// Compile-time Clebsch-Gordan coefficients (Condon-Shortley), double precision.
// ----------------------------------------------------------------------------
__host__ __device__ constexpr double cfact(int n) {
    double r = 1.0;
    for (int i = 2; i <= n; ++i) r *= (double)i;
    return r;
}

__host__ __device__ constexpr double csqrt(double x) {
    double g = (x > 1.0) ? x : 1.0;
    for (int i = 0; i < 60; ++i) g = 0.5 * (g + x / g);
    return g;
}

__host__ __device__ constexpr double cg_coef(int j1, int m1, int j2, int m2, int j, int m) {
    if (m1 + m2 != m) return 0.0;
    int dj = (j1 > j2) ? (j1 - j2) : (j2 - j1);
    if (j < dj || j > j1 + j2) return 0.0;
    double pref = csqrt((2.0 * j + 1.0)
        * cfact(j + j1 - j2) * cfact(j - j1 + j2) * cfact(j1 + j2 - j) / cfact(j1 + j2 + j + 1)
        * cfact(j + m) * cfact(j - m) * cfact(j1 - m1) * cfact(j1 + m1)
        * cfact(j2 - m2) * cfact(j2 + m2));
    int kmin = 0;
    if (j2 - j - m1 > kmin) kmin = j2 - j - m1;
    if (j1 - j + m2 > kmin) kmin = j1 - j + m2;
    int kmax = j1 + j2 - j;
    if (j1 - m1 < kmax) kmax = j1 - m1;
    if (j2 + m2 < kmax) kmax = j2 + m2;
    double s = 0.0;
    for (int k = kmin; k <= kmax; ++k) {
        double den = cfact(k) * cfact(j1 + j2 - j - k) * cfact(j1 - m1 - k)
                   * cfact(j2 + m2 - k) * cfact(j - j2 + m1 + k) * cfact(j - j1 - m2 + k);
        s += ((k & 1) ? -1.0 : 1.0) / den;
    }
    return pref * s;
}

// ----------------------------------------------------------------------------
// Compile-time unrolling with true constant indices.
// ----------------------------------------------------------------------------
template <int N, typename F>
__device__ __forceinline__ void static_for(F&& f) {
    if constexpr (N > 0) {
        static_for<N - 1>(f);
        f(std::integral_constant<int, N - 1>{});
    }
}

// ----------------------------------------------------------------------------
// Compile-time layout helpers.
// ----------------------------------------------------------------------------
__host__ __device__ __forceinline__ constexpr int part_index(int L1, int L2, int L) {
    int p = 0;
    for (int l1 = 0; l1 <= LMAX; ++l1)
        for (int l2 = 0; l2 <= LMAX; ++l2) {
            int lo = (l1 > l2) ? (l1 - l2) : (l2 - l1);
            int hi = (l1 + l2 < LMAX) ? (l1 + l2) : LMAX;
            if (L >= lo && L <= hi) {
                if (l1 == L1 && l2 == L2) return p;
                ++p;
            }
        }
    return 0;
}

__host__ __device__ __forceinline__ constexpr int npart(int l) {
    return (l == 0) ? 4 : (l == 1) ? 9 : (l == 2) ? 11 : 10;
}

__host__ __device__ __forceinline__ constexpr int lbase(int l) {
    int b = 0;
    for (int k = 0; k < l; ++k) b += 2 * NN * (2 * k + 1) * npart(k) * 256;
    return b;   // l0:0  l1:2097152  l2:16252928  l3:45088768
}

// ----------------------------------------------------------------------------
// One (l1,l2,l) TRIPLE for one n. Only 2*(2L+1) accumulators live.
// CG coefficients are FFMA immediates.
// ----------------------------------------------------------------------------
template <int L1, int L2, int L>
__device__ __forceinline__ void do_triple(
    const float* __restrict__ A, const float* __restrict__ B,
    float* __restrict__ out, int n, int tid)
{
    constexpr int D1 = 2 * L1 + 1;
    constexpr int D2 = 2 * L2 + 1;
    constexpr int DZ = 2 * L + 1;

    const int c = tid >> 4;
    const int d = tid & 15;

    float ar[D1], ai[D1], br[D2], bi[D2];
#pragma unroll
    for (int x = 0; x < D1; ++x) {
        ar[x] = __ldg(&A[(n * D1 + x) * TAU + c]);
        ai[x] = __ldg(&A[((NN + n) * D1 + x) * TAU + c]);
    }
#pragma unroll
    for (int y = 0; y < D2; ++y) {
        br[y] = __ldg(&B[(n * D2 + y) * TAU + d]);
        bi[y] = __ldg(&B[((NN + n) * D2 + y) * TAU + d]);
    }

    float accR[DZ], accI[DZ];
#pragma unroll
    for (int z = 0; z < DZ; ++z) { accR[z] = 0.f; accI[z] = 0.f; }

    static_for<D1>([&](auto XC) {
        constexpr int x = decltype(XC)::value;
        static_for<D2>([&](auto YC) {
            constexpr int y = decltype(YC)::value;
            constexpr int m = (x - L1) + (y - L2);
            if constexpr (m >= -L && m <= L) {
                constexpr float cg = (float)cg_coef(L1, x - L1, L2, y - L2, L, m);
                if constexpr (cg != 0.0f) {
                    const float pr = ar[x] * br[y] - ai[x] * bi[y];
                    const float pi = ar[x] * bi[y] + ai[x] * br[y];
                    accR[m + L] += cg * pr;   // FFMA with immediate
                    accI[m + L] += cg * pi;   // FFMA with immediate
                }
            }
        });
    });

    constexpr int taul  = npart(L) * 256;
    constexpr int pbase = lbase(L) + part_index(L1, L2, L) * 256;
    float* pR = out + pbase + tid + n * DZ * taul;
    float* pI = pR + NN * DZ * taul;
#pragma unroll
    for (int z = 0; z < DZ; ++z) {
        __stcs(pR + z * taul, accR[z]);   // real, streaming
        __stcs(pI + z * taul, accI[z]);   // imag, streaming
    }
}

// ----------------------------------------------------------------------------
// Main kernel: grid = (N, 34 triples), block = 256 threads (thread = channel).
// ----------------------------------------------------------------------------
__global__ __launch_bounds__(256, 5)
void cg_triple_kernel(
    const float* __restrict__ A0, const float* __restrict__ A1,
    const float* __restrict__ A2, const float* __restrict__ A3,
    const float* __restrict__ B0, const float* __restrict__ B1,
    const float* __restrict__ B2, const float* __restrict__ B3,
    float* __restrict__ out)
{
    const int n   = blockIdx.x;
    const int tid = threadIdx.x;

    switch (blockIdx.y) {
        case  0: do_triple<0, 0, 0>(A0, B0, out, n, tid); break;
        case  1: do_triple<0, 1, 1>(A0, B1, out, n, tid); break;
        case  2: do_triple<0, 2, 2>(A0, B2, out, n, tid); break;
        case  3: do_triple<0, 3, 3>(A0, B3, out, n, tid); break;
        case  4: do_triple<1, 0, 1>(A1, B0, out, n, tid); break;
        case  5: do_triple<1, 1, 0>(A1, B1, out, n, tid); break;
        case  6: do_triple<1, 1, 1>(A1, B1, out, n, tid); break;
        case  7: do_triple<1, 1, 2>(A1, B1, out, n, tid); break;
        case  8: do_triple<1, 2, 1>(A1, B2, out, n, tid); break;
        case  9: do_triple<1, 2, 2>(A1, B2, out, n, tid); break;
        case 10: do_triple<1, 2, 3>(A1, B2, out, n, tid); break;
        case 11: do_triple<1, 3, 2>(A1, B3, out, n, tid); break;
        case 12: do_triple<1, 3, 3>(A1, B3, out, n, tid); break;
        case 13: do_triple<2, 0, 2>(A2, B0, out, n, tid); break;
        case 14: do_triple<2, 1, 1>(A2, B1, out, n, tid); break;
        case 15: do_triple<2, 1, 2>(A2, B1, out, n, tid); break;
        case 16: do_triple<2, 1, 3>(A2, B1, out, n, tid); break;
        case 17: do_triple<2, 2, 0>(A2, B2, out, n, tid); break;
        case 18: do_triple<2, 2, 1>(A2, B2, out, n, tid); break;
        case 19: do_triple<2, 2, 2>(A2, B2, out, n, tid); break;
        case 20: do_triple<2, 2, 3>(A2, B2, out, n, tid); break;
        case 21: do_triple<2, 3, 1>(A2, B3, out, n, tid); break;
        case 22: do_triple<2, 3, 2>(A2, B3, out, n, tid); break;
        case 23: do_triple<2, 3, 3>(A2, B3, out, n, tid); break;
        case 24: do_triple<3, 0, 3>(A3, B0, out, n, tid); break;
        case 25: do_triple<3, 1, 2>(A3, B1, out, n, tid); break;
        case 26: do_triple<3, 1, 3>(A3, B1, out, n, tid); break;
        case 27: do_triple<3, 2, 1>(A3, B2, out, n, tid); break;
        case 28: do_triple<3, 2, 2>(A3, B2, out, n, tid); break;
        case 29: do_triple<3, 2, 3>(A3, B2, out, n, tid); break;
        case 30: do_triple<3, 3, 0>(A3, B3, out, n, tid); break;
        case 31: do_triple<3, 3, 1>(A3, B3, out, n, tid); break;
        case 32: do_triple<3, 3, 2>(A3, B3, out, n, tid); break;
        default: do_triple<3, 3, 3>(A3, B3, out, n, tid); break;
    }
}

// ----------------------------------------------------------------------------
// Launch: identify inputs by element count (A before B per degree — robust to
// either A0,B0,A1,B1,... or A0..A3,B0..B3 metadata ordering).
// ----------------------------------------------------------------------------
extern "C" void kernel_launch(void* const* d_in, const int* in_sizes, int n_in,
                              void* d_out, int out_size)
{
    const float* A[4] = {nullptr, nullptr, nullptr, nullptr};
    const float* B[4] = {nullptr, nullptr, nullptr, nullptr};
    for (int i = 0; i < n_in; ++i) {
        int sz = in_sizes[i];
        for (int l = 0; l <= LMAX; ++l) {
            if (sz == 2 * NN * (2 * l + 1) * TAU) {
                if (!A[l]) A[l] = (const float*)d_in[i];
                else if (!B[l]) B[l] = (const float*)d_in[i];
            }
        }
    }

    dim3 grid(NN, 34);
    cg_triple_kernel<<<grid, 256>>>(
        A[0], A[1], A[2], A[3],
        B[0], B[1], B[2], B[3],
        (float*)d_out);
}